// round 14
// baseline (speedup 1.0000x reference)
#include <cuda_runtime.h>
#include <cstdint>
#include <math.h>

#define Nb 512
#define Tt 64
#define Dd 512
#define Hh 512
#define FH 2048

// Persistent state (device globals: no allocations allowed)
__device__ float g_h[2][Nb * Hh];
__device__ float g_c[2][Nb * Hh];
__device__ float g_attn[Nb * Hh];
__device__ float g_xw[(size_t)Nb * Tt * FH];  // x @ Wx for ALL timesteps, row m = n*Tt + t

#define ASTR 20
#define BSTR 136
#define A_FLOATS (64 * ASTR)
#define STAGE_FLOATS (64 * ASTR + 16 * BSTR)  // 3456 floats
#define NSTAGES 3

#define CP_ASYNC16(dst, src) \
    asm volatile("cp.async.cg.shared.global [%0], [%1], 16;\n" :: "r"(dst), "l"(src))
#define CP_COMMIT() asm volatile("cp.async.commit_group;\n")
#define CP_WAIT1()  asm volatile("cp.async.wait_group 1;\n")

__device__ __forceinline__ uint32_t smem_u32(const void* p) {
    return (uint32_t)__cvta_generic_to_shared(p);
}
// PDL primitives (sm_90+): allow dependent grid to launch / wait for predecessor
__device__ __forceinline__ void pdl_trigger() {
    asm volatile("griddepcontrol.launch_dependents;" ::: "memory");
}
__device__ __forceinline__ void pdl_wait() {
    asm volatile("griddepcontrol.wait;" ::: "memory");
}

// ---------------------------------------------------------------------------
// init: h0 = c0 = mean over the 16 spatial positions of A
// ---------------------------------------------------------------------------
__global__ __launch_bounds__(128) void init_kernel(const float* __restrict__ A) {
    int n = blockIdx.x, tid = threadIdx.x;
    const float4* base = (const float4*)(A + (size_t)n * Hh * 16);
#pragma unroll
    for (int i = 0; i < 4; i++) {
        int r = tid + i * 128;
        float4 v0 = base[r * 4 + 0], v1 = base[r * 4 + 1];
        float4 v2 = base[r * 4 + 2], v3 = base[r * 4 + 3];
        float s = (v0.x + v0.y + v0.z + v0.w) + (v1.x + v1.y + v1.z + v1.w)
                + (v2.x + v2.y + v2.z + v2.w) + (v3.x + v3.y + v3.z + v3.w);
        float m = s * (1.0f / 16.0f);
        g_h[0][n * Hh + r] = m;
        g_c[0][n * Hh + r] = m;
    }
}

// ---------------------------------------------------------------------------
// ONE-TIME big GEMM: g_xw = x @ Wx for all (n,t) rows. M = Nb*Tt = 32768.
// ---------------------------------------------------------------------------
__global__ __launch_bounds__(256, 2) void xw_all_kernel(
    const float* __restrict__ x, const float* __restrict__ Wx)
{
    __shared__ __align__(16) float sm[NSTAGES * STAGE_FLOATS];
    const int tid = threadIdx.x;
    const int j0 = blockIdx.x * 32;
    const int m0 = blockIdx.y * 64;
    const float* xbase = x + (size_t)m0 * Dd;
    const int am = tid >> 2, akq = (tid & 3) * 4;

    const int lane = tid & 31, wid = tid >> 5;
    const int wm = wid & 1, wn = wid >> 1;
    const int gid = lane >> 2, tg = lane & 3;

    float acc[2][4][4];
#pragma unroll
    for (int fm = 0; fm < 2; fm++)
#pragma unroll
        for (int fn = 0; fn < 4; fn++)
#pragma unroll
            for (int e = 0; e < 4; e++) acc[fm][fn][e] = 0.f;

    auto issue = [&](int i) {
        float* stg = sm + (i % NSTAGES) * STAGE_FLOATS;
        int kl = i << 4;
        const float* asrc = xbase + (size_t)am * Dd + kl + akq;
        CP_ASYNC16(smem_u32(stg + am * ASTR + akq), asrc);
        float* Bst = stg + A_FLOATS;
#pragma unroll
        for (int j = 0; j < 2; j++) {
            int e = tid + j * 256;
            int k = e >> 5, n4 = e & 31;
            const float* bsrc = Wx + (size_t)(kl + k) * FH + (n4 >> 3) * 512 + j0 + (n4 & 7) * 4;
            CP_ASYNC16(smem_u32(Bst + k * BSTR + n4 * 4), bsrc);
        }
    };

    issue(0); CP_COMMIT();
    issue(1); CP_COMMIT();

    for (int i = 0; i < 32; i++) {
        CP_WAIT1();
        __syncthreads();
        const float* As = sm + (i % NSTAGES) * STAGE_FLOATS;
        const float* Bs = As + A_FLOATS;
#pragma unroll
        for (int k8 = 0; k8 < 2; k8++) {
            int kb = k8 * 8;
            uint32_t a[2][4], bf[4][2];
#pragma unroll
            for (int fm = 0; fm < 2; fm++) {
                int row = wm * 32 + fm * 16 + gid;
                a[fm][0] = __float_as_uint(As[row * ASTR + kb + tg]);
                a[fm][1] = __float_as_uint(As[(row + 8) * ASTR + kb + tg]);
                a[fm][2] = __float_as_uint(As[row * ASTR + kb + tg + 4]);
                a[fm][3] = __float_as_uint(As[(row + 8) * ASTR + kb + tg + 4]);
            }
#pragma unroll
            for (int fn = 0; fn < 4; fn++) {
                int col = wn * 32 + fn * 8 + gid;
                bf[fn][0] = __float_as_uint(Bs[(kb + tg) * BSTR + col]);
                bf[fn][1] = __float_as_uint(Bs[(kb + tg + 4) * BSTR + col]);
            }
#pragma unroll
            for (int fm = 0; fm < 2; fm++)
#pragma unroll
                for (int fn = 0; fn < 4; fn++) {
                    asm volatile(
                        "mma.sync.aligned.m16n8k8.row.col.f32.tf32.tf32.f32 "
                        "{%0,%1,%2,%3}, {%4,%5,%6,%7}, {%8,%9}, {%0,%1,%2,%3};\n"
                        : "+f"(acc[fm][fn][0]), "+f"(acc[fm][fn][1]),
                          "+f"(acc[fm][fn][2]), "+f"(acc[fm][fn][3])
                        : "r"(a[fm][0]), "r"(a[fm][1]), "r"(a[fm][2]), "r"(a[fm][3]),
                          "r"(bf[fn][0]), "r"(bf[fn][1]));
                }
        }
        if (i + 2 < 32) issue(i + 2);
        CP_COMMIT();
    }

#pragma unroll
    for (int fm = 0; fm < 2; fm++)
#pragma unroll
        for (int fn = 0; fn < 4; fn++) {
            int R = wm * 32 + fm * 16 + gid;
            int fc = wn * 512 + j0 + fn * 8 + tg * 2;
            *(float2*)&g_xw[(size_t)(m0 + R) * FH + fc] =
                make_float2(acc[fm][fn][0], acc[fm][fn][1]);
            *(float2*)&g_xw[(size_t)(m0 + R + 8) * FH + fc] =
                make_float2(acc[fm][fn][2], acc[fm][fn][3]);
        }
}

// ---------------------------------------------------------------------------
// attention with PDL: A-stream (16.7 MB) loaded BEFORE griddepcontrol.wait,
// overlapping the previous step kernel. h read + compute after wait.
// ---------------------------------------------------------------------------
__global__ __launch_bounds__(128) void attn_kernel(const float* __restrict__ A, int pi) {
    pdl_trigger();   // let the following step kernel launch early

    int n = blockIdx.x, tid = threadIdx.x;
    int lane = tid & 31, warp = tid >> 5;
    const float4* base = (const float4*)(A + (size_t)n * Hh * 16);

    // ---- pre-sync: stream this row's A into registers (no sequential dep)
    float Av[4][16];
#pragma unroll
    for (int i = 0; i < 4; i++) {
        int r = tid + i * 128;
#pragma unroll
        for (int q = 0; q < 4; q++) {
            float4 v = base[r * 4 + q];
            Av[i][q * 4 + 0] = v.x; Av[i][q * 4 + 1] = v.y;
            Av[i][q * 4 + 2] = v.z; Av[i][q * 4 + 3] = v.w;
        }
    }

    pdl_wait();      // previous step kernel complete -> g_h[pi] valid

    const float* hbuf = g_h[pi] + (size_t)n * Hh;
    float hv[4];
    float part[16];
#pragma unroll
    for (int p = 0; p < 16; p++) part[p] = 0.f;
#pragma unroll
    for (int i = 0; i < 4; i++) {
        hv[i] = hbuf[tid + i * 128];
#pragma unroll
        for (int p = 0; p < 16; p++) part[p] += hv[i] * Av[i][p];
    }

#pragma unroll
    for (int off = 16; off >= 1; off >>= 1)
#pragma unroll
        for (int p = 0; p < 16; p++)
            part[p] += __shfl_xor_sync(0xffffffffu, part[p], off);

    __shared__ float red[4][16];
    __shared__ float w[16];
    if (lane == 0) {
#pragma unroll
        for (int p = 0; p < 16; p++) red[warp][p] = part[p];
    }
    __syncthreads();
    if (tid == 0) {
        const float scale = 0.044194173824159216f;  // 1/sqrt(512)
        float sc[16];
        float mx = -1e30f;
#pragma unroll
        for (int p = 0; p < 16; p++) {
            sc[p] = (red[0][p] + red[1][p] + red[2][p] + red[3][p]) * scale;
            mx = fmaxf(mx, sc[p]);
        }
        float s = 0.f;
#pragma unroll
        for (int p = 0; p < 16; p++) { float e = expf(sc[p] - mx); w[p] = e; s += e; }
        float inv = 1.f / s;
#pragma unroll
        for (int p = 0; p < 16; p++) w[p] *= inv;
    }
    __syncthreads();

    float wl[16];
#pragma unroll
    for (int p = 0; p < 16; p++) wl[p] = w[p];
    float* ao = g_attn + (size_t)n * Hh;
#pragma unroll
    for (int i = 0; i < 4; i++) {
        float s = 0.f;
#pragma unroll
        for (int p = 0; p < 16; p++) s += Av[i][p] * wl[p];
        ao[tid + i * 128] = s;
    }
}

// ---------------------------------------------------------------------------
// sequential step with PDL: acc-init from g_xw (static) before wait;
// h/attn/c consumed after wait. Round-4 proven mainloop + gate epilogue.
// ---------------------------------------------------------------------------
__global__ __launch_bounds__(256, 1) void step_kernel(
    const float* __restrict__ Wh, const float* __restrict__ Wattn,
    const float* __restrict__ bias, float* __restrict__ out, int t, int pi)
{
    pdl_trigger();   // let the next attn kernel launch early

    __shared__ __align__(16) float sm[NSTAGES * STAGE_FLOATS];
    const int tid = threadIdx.x;
    const int j0 = blockIdx.x * 32;
    const int n0 = blockIdx.y * 64;

    const int am = tid >> 2, akq = (tid & 3) * 4;
    const int lane = tid & 31, wid = tid >> 5;
    const int wm = wid & 1, wn = wid >> 1;
    const int gid = lane >> 2, tg = lane & 3;

    // ---- pre-sync: acc init from g_xw (written by xw_all, long complete)
    float acc[2][4][4];
#pragma unroll
    for (int fm = 0; fm < 2; fm++)
#pragma unroll
        for (int fn = 0; fn < 4; fn++) {
            int R = wm * 32 + fm * 16 + gid;
            int fc = wn * 512 + j0 + fn * 8 + tg * 2;
            float2 v0 = *(const float2*)&g_xw[((size_t)(n0 + R) * Tt + t) * FH + fc];
            float2 v1 = *(const float2*)&g_xw[((size_t)(n0 + R + 8) * Tt + t) * FH + fc];
            acc[fm][fn][0] = v0.x; acc[fm][fn][1] = v0.y;
            acc[fm][fn][2] = v1.x; acc[fm][fn][3] = v1.y;
        }

    pdl_wait();      // attn kernel complete -> g_attn, g_h[pi], g_c[pi] valid

    const float* h_in = g_h[pi];
    const float* c_in = g_c[pi];
    float* h_out = g_h[pi ^ 1];
    float* c_out = g_c[pi ^ 1];

    auto issue = [&](int i) {
        float* stg = sm + (i % NSTAGES) * STAGE_FLOATS;
        int seg = i >> 5;
        int kl = (i & 31) << 4;
        const float* Ab; const float* W;
        if (seg == 0) { Ab = h_in   + (size_t)n0 * Hh; W = Wh; }
        else          { Ab = g_attn + (size_t)n0 * Hh; W = Wattn; }
        const float* asrc = Ab + (size_t)am * Hh + kl + akq;
        CP_ASYNC16(smem_u32(stg + am * ASTR + akq), asrc);
        float* Bst = stg + A_FLOATS;
#pragma unroll
        for (int j = 0; j < 2; j++) {
            int e = tid + j * 256;
            int k = e >> 5, n4 = e & 31;
            const float* bsrc = W + (size_t)(kl + k) * FH + (n4 >> 3) * 512 + j0 + (n4 & 7) * 4;
            CP_ASYNC16(smem_u32(Bst + k * BSTR + n4 * 4), bsrc);
        }
    };

    issue(0); CP_COMMIT();
    issue(1); CP_COMMIT();

    for (int i = 0; i < 64; i++) {
        CP_WAIT1();
        __syncthreads();
        const float* As = sm + (i % NSTAGES) * STAGE_FLOATS;
        const float* Bs = As + A_FLOATS;
#pragma unroll
        for (int k8 = 0; k8 < 2; k8++) {
            int kb = k8 * 8;
            uint32_t a[2][4], bf[4][2];
#pragma unroll
            for (int fm = 0; fm < 2; fm++) {
                int row = wm * 32 + fm * 16 + gid;
                a[fm][0] = __float_as_uint(As[row * ASTR + kb + tg]);
                a[fm][1] = __float_as_uint(As[(row + 8) * ASTR + kb + tg]);
                a[fm][2] = __float_as_uint(As[row * ASTR + kb + tg + 4]);
                a[fm][3] = __float_as_uint(As[(row + 8) * ASTR + kb + tg + 4]);
            }
#pragma unroll
            for (int fn = 0; fn < 4; fn++) {
                int col = wn * 32 + fn * 8 + gid;
                bf[fn][0] = __float_as_uint(Bs[(kb + tg) * BSTR + col]);
                bf[fn][1] = __float_as_uint(Bs[(kb + tg + 4) * BSTR + col]);
            }
#pragma unroll
            for (int fm = 0; fm < 2; fm++)
#pragma unroll
                for (int fn = 0; fn < 4; fn++) {
                    asm volatile(
                        "mma.sync.aligned.m16n8k8.row.col.f32.tf32.tf32.f32 "
                        "{%0,%1,%2,%3}, {%4,%5,%6,%7}, {%8,%9}, {%0,%1,%2,%3};\n"
                        : "+f"(acc[fm][fn][0]), "+f"(acc[fm][fn][1]),
                          "+f"(acc[fm][fn][2]), "+f"(acc[fm][fn][3])
                        : "r"(a[fm][0]), "r"(a[fm][1]), "r"(a[fm][2]), "r"(a[fm][3]),
                          "r"(bf[fn][0]), "r"(bf[fn][1]));
                }
        }
        if (i + 2 < 64) issue(i + 2);
        CP_COMMIT();
    }

    __syncthreads();
    float (*atile)[132] = (float(*)[132])sm;
#pragma unroll
    for (int fm = 0; fm < 2; fm++)
#pragma unroll
        for (int fn = 0; fn < 4; fn++) {
            int R = wm * 32 + fm * 16 + gid, C = wn * 32 + fn * 8 + tg * 2;
            atile[R][C]         = acc[fm][fn][0];
            atile[R][C + 1]     = acc[fm][fn][1];
            atile[R + 8][C]     = acc[fm][fn][2];
            atile[R + 8][C + 1] = acc[fm][fn][3];
        }
    __syncthreads();

    {
        int col = tid & 31;
        int r0 = tid >> 5;
        float bi = bias[j0 + col];
        float bff = bias[512 + j0 + col];
        float bo = bias[1024 + j0 + col];
        float bg = bias[1536 + j0 + col];
#pragma unroll
        for (int q = 0; q < 8; q++) {
            int row = r0 + q * 8;
            float vi = atile[row][col]      + bi;
            float vf = atile[row][col + 32] + bff;
            float vo = atile[row][col + 64] + bo;
            float vg = atile[row][col + 96] + bg;
            float ig = 1.f / (1.f + expf(-vi));
            float fg = 1.f / (1.f + expf(-vf));
            float og = 1.f / (1.f + expf(-vo));
            float gg = tanhf(vg);
            int n = n0 + row, hc = j0 + col;
            float cold = c_in[n * Hh + hc];
            float cn = fg * cold + ig * gg;
            float hn = og * tanhf(cn);
            c_out[n * Hh + hc] = cn;
            h_out[n * Hh + hc] = hn;
            out[((size_t)n * Tt + t) * Hh + hc] = hn;
        }
    }
}

// ---------------------------------------------------------------------------
static void launch_pdl(const void* fn, dim3 grid, dim3 block, void** args) {
    cudaLaunchConfig_t cfg = {};
    cfg.gridDim = grid;
    cfg.blockDim = block;
    cfg.dynamicSmemBytes = 0;
    cfg.stream = 0;
    cudaLaunchAttribute attr[1];
    attr[0].id = cudaLaunchAttributeProgrammaticStreamSerialization;
    attr[0].val.programmaticStreamSerializationAllowed = 1;
    cfg.attrs = attr;
    cfg.numAttrs = 1;
    cudaLaunchKernelExC(&cfg, fn, args);
}

extern "C" void kernel_launch(void* const* d_in, const int* in_sizes, int n_in,
                              void* d_out, int out_size) {
    const float* x     = (const float*)d_in[0];
    const float* A     = (const float*)d_in[1];
    const float* Wx    = (const float*)d_in[2];
    const float* Wh    = (const float*)d_in[3];
    const float* Wattn = (const float*)d_in[4];
    const float* b     = (const float*)d_in[5];
    float* out = (float*)d_out;

    xw_all_kernel<<<dim3(16, 512), 256>>>(x, Wx);
    init_kernel<<<Nb, 128>>>(A);

    for (int t = 0; t < Tt; t++) {
        int pi = t & 1;
        {
            void* args[2] = {(void*)&A, (void*)&pi};
            launch_pdl((const void*)attn_kernel, dim3(Nb), dim3(128), args);
        }
        {
            void* args[6] = {(void*)&Wh, (void*)&Wattn, (void*)&b,
                             (void*)&out, (void*)&t, (void*)&pi};
            launch_pdl((const void*)step_kernel, dim3(16, 8), dim3(256), args);
        }
    }
}

// round 15
// speedup vs baseline: 1.4463x; 1.4463x over previous
#include <cuda_runtime.h>
#include <cstdint>
#include <math.h>

#define Nb 512
#define Tt 64
#define Dd 512
#define Hh 512
#define FH 2048

// Persistent state (device globals: no allocations allowed)
__device__ float g_h[2][Nb * Hh];
__device__ float g_c[2][Nb * Hh];
__device__ float g_attn[Nb * Hh];
__device__ float g_xw[(size_t)Nb * Tt * FH];  // x @ Wx for ALL timesteps, row m = n*Tt + t

// ---- xw_all staging (K=16/stage, round-4 proven) ----
#define ASTR 20
#define BSTR 136
#define A_FLOATS (64 * ASTR)
#define STAGE_FLOATS (64 * ASTR + 16 * BSTR)  // 3456 floats
#define NSTAGES 3

// ---- step staging (K=32/stage) ----
#define ASTR2 36
#define A2_FLOATS (64 * ASTR2)                    // 2304
#define STAGE2_FLOATS (64 * ASTR2 + 32 * BSTR)    // 2304 + 4352 = 6656 floats
// step smem: 3 stages = 19968 floats (80KB); epilogue atile 64*132=8448 fits inside

#define CP_ASYNC16(dst, src) \
    asm volatile("cp.async.cg.shared.global [%0], [%1], 16;\n" :: "r"(dst), "l"(src))
#define CP_COMMIT() asm volatile("cp.async.commit_group;\n")
#define CP_WAIT1()  asm volatile("cp.async.wait_group 1;\n")

__device__ __forceinline__ uint32_t smem_u32(const void* p) {
    return (uint32_t)__cvta_generic_to_shared(p);
}

// ---------------------------------------------------------------------------
// init: h0 = c0 = mean over the 16 spatial positions of A
// ---------------------------------------------------------------------------
__global__ __launch_bounds__(128) void init_kernel(const float* __restrict__ A) {
    int n = blockIdx.x, tid = threadIdx.x;
    const float4* base = (const float4*)(A + (size_t)n * Hh * 16);
#pragma unroll
    for (int i = 0; i < 4; i++) {
        int r = tid + i * 128;
        float4 v0 = base[r * 4 + 0], v1 = base[r * 4 + 1];
        float4 v2 = base[r * 4 + 2], v3 = base[r * 4 + 3];
        float s = (v0.x + v0.y + v0.z + v0.w) + (v1.x + v1.y + v1.z + v1.w)
                + (v2.x + v2.y + v2.z + v2.w) + (v3.x + v3.y + v3.z + v3.w);
        float m = s * (1.0f / 16.0f);
        g_h[0][n * Hh + r] = m;
        g_c[0][n * Hh + r] = m;
    }
}

// ---------------------------------------------------------------------------
// ONE-TIME big GEMM: g_xw = x @ Wx for all (n,t) rows. M = Nb*Tt = 32768.
// Grid (16, 512) = 8192 CTAs; proven round-4 CTA body, 32 K-iters, 2 CTAs/SM.
// ---------------------------------------------------------------------------
__global__ __launch_bounds__(256, 2) void xw_all_kernel(
    const float* __restrict__ x, const float* __restrict__ Wx)
{
    __shared__ __align__(16) float sm[NSTAGES * STAGE_FLOATS];
    const int tid = threadIdx.x;
    const int j0 = blockIdx.x * 32;
    const int m0 = blockIdx.y * 64;
    const float* xbase = x + (size_t)m0 * Dd;
    const int am = tid >> 2, akq = (tid & 3) * 4;

    const int lane = tid & 31, wid = tid >> 5;
    const int wm = wid & 1, wn = wid >> 1;
    const int gid = lane >> 2, tg = lane & 3;

    float acc[2][4][4];
#pragma unroll
    for (int fm = 0; fm < 2; fm++)
#pragma unroll
        for (int fn = 0; fn < 4; fn++)
#pragma unroll
            for (int e = 0; e < 4; e++) acc[fm][fn][e] = 0.f;

    auto issue = [&](int i) {
        float* stg = sm + (i % NSTAGES) * STAGE_FLOATS;
        int kl = i << 4;
        const float* asrc = xbase + (size_t)am * Dd + kl + akq;
        CP_ASYNC16(smem_u32(stg + am * ASTR + akq), asrc);
        float* Bst = stg + A_FLOATS;
#pragma unroll
        for (int j = 0; j < 2; j++) {
            int e = tid + j * 256;
            int k = e >> 5, n4 = e & 31;
            const float* bsrc = Wx + (size_t)(kl + k) * FH + (n4 >> 3) * 512 + j0 + (n4 & 7) * 4;
            CP_ASYNC16(smem_u32(Bst + k * BSTR + n4 * 4), bsrc);
        }
    };

    issue(0); CP_COMMIT();
    issue(1); CP_COMMIT();

    for (int i = 0; i < 32; i++) {
        CP_WAIT1();
        __syncthreads();
        const float* As = sm + (i % NSTAGES) * STAGE_FLOATS;
        const float* Bs = As + A_FLOATS;
#pragma unroll
        for (int k8 = 0; k8 < 2; k8++) {
            int kb = k8 * 8;
            uint32_t a[2][4], bf[4][2];
#pragma unroll
            for (int fm = 0; fm < 2; fm++) {
                int row = wm * 32 + fm * 16 + gid;
                a[fm][0] = __float_as_uint(As[row * ASTR + kb + tg]);
                a[fm][1] = __float_as_uint(As[(row + 8) * ASTR + kb + tg]);
                a[fm][2] = __float_as_uint(As[row * ASTR + kb + tg + 4]);
                a[fm][3] = __float_as_uint(As[(row + 8) * ASTR + kb + tg + 4]);
            }
#pragma unroll
            for (int fn = 0; fn < 4; fn++) {
                int col = wn * 32 + fn * 8 + gid;
                bf[fn][0] = __float_as_uint(Bs[(kb + tg) * BSTR + col]);
                bf[fn][1] = __float_as_uint(Bs[(kb + tg + 4) * BSTR + col]);
            }
#pragma unroll
            for (int fm = 0; fm < 2; fm++)
#pragma unroll
                for (int fn = 0; fn < 4; fn++) {
                    asm volatile(
                        "mma.sync.aligned.m16n8k8.row.col.f32.tf32.tf32.f32 "
                        "{%0,%1,%2,%3}, {%4,%5,%6,%7}, {%8,%9}, {%0,%1,%2,%3};\n"
                        : "+f"(acc[fm][fn][0]), "+f"(acc[fm][fn][1]),
                          "+f"(acc[fm][fn][2]), "+f"(acc[fm][fn][3])
                        : "r"(a[fm][0]), "r"(a[fm][1]), "r"(a[fm][2]), "r"(a[fm][3]),
                          "r"(bf[fn][0]), "r"(bf[fn][1]));
                }
        }
        if (i + 2 < 32) issue(i + 2);
        CP_COMMIT();
    }

#pragma unroll
    for (int fm = 0; fm < 2; fm++)
#pragma unroll
        for (int fn = 0; fn < 4; fn++) {
            int R = wm * 32 + fm * 16 + gid;
            int fc = wn * 512 + j0 + fn * 8 + tg * 2;
            *(float2*)&g_xw[(size_t)(m0 + R) * FH + fc] =
                make_float2(acc[fm][fn][0], acc[fm][fn][1]);
            *(float2*)&g_xw[(size_t)(m0 + R + 8) * FH + fc] =
                make_float2(acc[fm][fn][2], acc[fm][fn][3]);
        }
}

// ---------------------------------------------------------------------------
// attention (proven round-4 version): one block per batch row, 128 threads,
// A row in registers, read once.
// ---------------------------------------------------------------------------
__global__ __launch_bounds__(128) void attn_kernel(const float* __restrict__ A, int pi) {
    int n = blockIdx.x, tid = threadIdx.x;
    int lane = tid & 31, warp = tid >> 5;
    const float* hbuf = g_h[pi] + (size_t)n * Hh;
    const float4* base = (const float4*)(A + (size_t)n * Hh * 16);

    float Av[4][16];
    float hv[4];
    float part[16];
#pragma unroll
    for (int p = 0; p < 16; p++) part[p] = 0.f;

#pragma unroll
    for (int i = 0; i < 4; i++) {
        int r = tid + i * 128;
#pragma unroll
        for (int q = 0; q < 4; q++) {
            float4 v = base[r * 4 + q];
            Av[i][q * 4 + 0] = v.x; Av[i][q * 4 + 1] = v.y;
            Av[i][q * 4 + 2] = v.z; Av[i][q * 4 + 3] = v.w;
        }
        hv[i] = hbuf[r];
#pragma unroll
        for (int p = 0; p < 16; p++) part[p] += hv[i] * Av[i][p];
    }

#pragma unroll
    for (int off = 16; off >= 1; off >>= 1)
#pragma unroll
        for (int p = 0; p < 16; p++)
            part[p] += __shfl_xor_sync(0xffffffffu, part[p], off);

    __shared__ float red[4][16];
    __shared__ float w[16];
    if (lane == 0) {
#pragma unroll
        for (int p = 0; p < 16; p++) red[warp][p] = part[p];
    }
    __syncthreads();
    if (tid == 0) {
        const float scale = 0.044194173824159216f;  // 1/sqrt(512)
        float sc[16];
        float mx = -1e30f;
#pragma unroll
        for (int p = 0; p < 16; p++) {
            sc[p] = (red[0][p] + red[1][p] + red[2][p] + red[3][p]) * scale;
            mx = fmaxf(mx, sc[p]);
        }
        float s = 0.f;
#pragma unroll
        for (int p = 0; p < 16; p++) { float e = expf(sc[p] - mx); w[p] = e; s += e; }
        float inv = 1.f / s;
#pragma unroll
        for (int p = 0; p < 16; p++) w[p] *= inv;
    }
    __syncthreads();

    float wl[16];
#pragma unroll
    for (int p = 0; p < 16; p++) wl[p] = w[p];
    float* ao = g_attn + (size_t)n * Hh;
#pragma unroll
    for (int i = 0; i < 4; i++) {
        float s = 0.f;
#pragma unroll
        for (int p = 0; p < 16; p++) s += Av[i][p] * wl[p];
        ao[tid + i * 128] = s;
    }
}

// ---------------------------------------------------------------------------
// sequential step: K=1024 in 32 iterations of K=32 (halved barrier count,
// doubled per-iter ILP). acc initialized from g_xw (row n*Tt + t).
// Same MMA sequence/order as before -> identical numerics.
// ---------------------------------------------------------------------------
__global__ __launch_bounds__(256, 1) void step_kernel(
    const float* __restrict__ Wh, const float* __restrict__ Wattn,
    const float* __restrict__ bias, float* __restrict__ out, int t, int pi)
{
    __shared__ __align__(16) float sm[NSTAGES * STAGE2_FLOATS];
    const int tid = threadIdx.x;
    const int j0 = blockIdx.x * 32;
    const int n0 = blockIdx.y * 64;
    const float* h_in = g_h[pi];
    const float* c_in = g_c[pi];
    float* h_out = g_h[pi ^ 1];
    float* c_out = g_c[pi ^ 1];

    const int lane = tid & 31, wid = tid >> 5;
    const int wm = wid & 1, wn = wid >> 1;
    const int gid = lane >> 2, tg = lane & 3;

    // acc init from g_xw (row m = n*Tt + t)
    float acc[2][4][4];
#pragma unroll
    for (int fm = 0; fm < 2; fm++)
#pragma unroll
        for (int fn = 0; fn < 4; fn++) {
            int R = wm * 32 + fm * 16 + gid;
            int fc = wn * 512 + j0 + fn * 8 + tg * 2;
            float2 v0 = *(const float2*)&g_xw[((size_t)(n0 + R) * Tt + t) * FH + fc];
            float2 v1 = *(const float2*)&g_xw[((size_t)(n0 + R + 8) * Tt + t) * FH + fc];
            acc[fm][fn][0] = v0.x; acc[fm][fn][1] = v0.y;
            acc[fm][fn][2] = v1.x; acc[fm][fn][3] = v1.y;
        }

    // stage issue: K=32 slab. A tile 64x32 (2 chunks/thread), B tile 32x128
    // (4 chunks/thread).
    auto issue = [&](int i) {
        float* stg = sm + (i % NSTAGES) * STAGE2_FLOATS;
        int seg = i >> 4;                 // 0..15 -> h/Wh, 16..31 -> attn/Wattn
        int kl = (i & 15) << 5;           // K offset within segment
        const float* Ab; const float* W;
        if (seg == 0) { Ab = h_in   + (size_t)n0 * Hh; W = Wh; }
        else          { Ab = g_attn + (size_t)n0 * Hh; W = Wattn; }
#pragma unroll
        for (int j = 0; j < 2; j++) {
            int e = tid + j * 256;
            int row = e >> 3, kc = e & 7;   // 64 rows x 8 chunks
            const float* asrc = Ab + (size_t)row * Hh + kl + kc * 4;
            CP_ASYNC16(smem_u32(stg + row * ASTR2 + kc * 4), asrc);
        }
        float* Bst = stg + A2_FLOATS;
#pragma unroll
        for (int j = 0; j < 4; j++) {
            int e = tid + j * 256;
            int k = e >> 5, n4 = e & 31;    // 32 k-rows x 32 chunks
            const float* bsrc = W + (size_t)(kl + k) * FH + (n4 >> 3) * 512 + j0 + (n4 & 7) * 4;
            CP_ASYNC16(smem_u32(Bst + k * BSTR + n4 * 4), bsrc);
        }
    };

    issue(0); CP_COMMIT();
    issue(1); CP_COMMIT();

    for (int i = 0; i < 32; i++) {
        CP_WAIT1();
        __syncthreads();
        const float* As = sm + (i % NSTAGES) * STAGE2_FLOATS;
        const float* Bs = As + A2_FLOATS;
#pragma unroll
        for (int k8 = 0; k8 < 4; k8++) {
            int kb = k8 * 8;
            uint32_t a[2][4], bf[4][2];
#pragma unroll
            for (int fm = 0; fm < 2; fm++) {
                int row = wm * 32 + fm * 16 + gid;
                a[fm][0] = __float_as_uint(As[row * ASTR2 + kb + tg]);
                a[fm][1] = __float_as_uint(As[(row + 8) * ASTR2 + kb + tg]);
                a[fm][2] = __float_as_uint(As[row * ASTR2 + kb + tg + 4]);
                a[fm][3] = __float_as_uint(As[(row + 8) * ASTR2 + kb + tg + 4]);
            }
#pragma unroll
            for (int fn = 0; fn < 4; fn++) {
                int col = wn * 32 + fn * 8 + gid;
                bf[fn][0] = __float_as_uint(Bs[(kb + tg) * BSTR + col]);
                bf[fn][1] = __float_as_uint(Bs[(kb + tg + 4) * BSTR + col]);
            }
#pragma unroll
            for (int fm = 0; fm < 2; fm++)
#pragma unroll
                for (int fn = 0; fn < 4; fn++) {
                    asm volatile(
                        "mma.sync.aligned.m16n8k8.row.col.f32.tf32.tf32.f32 "
                        "{%0,%1,%2,%3}, {%4,%5,%6,%7}, {%8,%9}, {%0,%1,%2,%3};\n"
                        : "+f"(acc[fm][fn][0]), "+f"(acc[fm][fn][1]),
                          "+f"(acc[fm][fn][2]), "+f"(acc[fm][fn][3])
                        : "r"(a[fm][0]), "r"(a[fm][1]), "r"(a[fm][2]), "r"(a[fm][3]),
                          "r"(bf[fn][0]), "r"(bf[fn][1]));
                }
        }
        if (i + 2 < 32) issue(i + 2);
        CP_COMMIT();
    }

    __syncthreads();
    // stash a-tile (64 x 128) in smem for gate gathering
    float (*atile)[132] = (float(*)[132])sm;
#pragma unroll
    for (int fm = 0; fm < 2; fm++)
#pragma unroll
        for (int fn = 0; fn < 4; fn++) {
            int R = wm * 32 + fm * 16 + gid, C = wn * 32 + fn * 8 + tg * 2;
            atile[R][C]         = acc[fm][fn][0];
            atile[R][C + 1]     = acc[fm][fn][1];
            atile[R + 8][C]     = acc[fm][fn][2];
            atile[R + 8][C + 1] = acc[fm][fn][3];
        }
    __syncthreads();

    {
        int col = tid & 31;
        int r0 = tid >> 5;
        float bi = bias[j0 + col];
        float bff = bias[512 + j0 + col];
        float bo = bias[1024 + j0 + col];
        float bg = bias[1536 + j0 + col];
#pragma unroll
        for (int q = 0; q < 8; q++) {
            int row = r0 + q * 8;
            float vi = atile[row][col]      + bi;
            float vf = atile[row][col + 32] + bff;
            float vo = atile[row][col + 64] + bo;
            float vg = atile[row][col + 96] + bg;
            float ig = 1.f / (1.f + expf(-vi));
            float fg = 1.f / (1.f + expf(-vf));
            float og = 1.f / (1.f + expf(-vo));
            float gg = tanhf(vg);
            int n = n0 + row, hc = j0 + col;
            float cold = c_in[n * Hh + hc];
            float cn = fg * cold + ig * gg;
            float hn = og * tanhf(cn);
            c_out[n * Hh + hc] = cn;
            h_out[n * Hh + hc] = hn;
            out[((size_t)n * Tt + t) * Hh + hc] = hn;
        }
    }
}

// ---------------------------------------------------------------------------
extern "C" void kernel_launch(void* const* d_in, const int* in_sizes, int n_in,
                              void* d_out, int out_size) {
    const float* x     = (const float*)d_in[0];
    const float* A     = (const float*)d_in[1];
    const float* Wx    = (const float*)d_in[2];
    const float* Wh    = (const float*)d_in[3];
    const float* Wattn = (const float*)d_in[4];
    const float* b     = (const float*)d_in[5];
    float* out = (float*)d_out;

    xw_all_kernel<<<dim3(16, 512), 256>>>(x, Wx);   // no deps on the recurrence
    init_kernel<<<Nb, 128>>>(A);
    for (int t = 0; t < Tt; t++) {
        int pi = t & 1;
        attn_kernel<<<Nb, 128>>>(A, pi);
        step_kernel<<<dim3(16, 8), 256>>>(Wh, Wattn, b, out, t, pi);
    }
}

// round 16
// speedup vs baseline: 1.4826x; 1.0250x over previous
#include <cuda_runtime.h>
#include <cstdint>
#include <math.h>

#define Nb 512
#define Tt 64
#define Dd 512
#define Hh 512
#define FH 2048

// Persistent state (device globals: no allocations allowed)
__device__ float g_h[2][Nb * Hh];
__device__ float g_c[2][Nb * Hh];
__device__ float g_attn[Nb * Hh];
__device__ float g_xw[(size_t)Nb * Tt * FH];  // x @ Wx for ALL timesteps, row m = n*Tt + t

// ---- xw_all staging (K=16/stage, round-4 proven) ----
#define ASTR 20
#define BSTR 136
#define A_FLOATS (64 * ASTR)
#define STAGE_FLOATS (64 * ASTR + 16 * BSTR)  // 3456 floats
#define NSTAGES 3

// ---- step staging (K=64/stage) ----
#define ASTR3 68
#define A3_FLOATS (64 * ASTR3)                    // 4352
#define STAGE3_FLOATS (64 * ASTR3 + 64 * BSTR)    // 4352 + 8704 = 13056 floats
#define STEP_SMEM_BYTES (3 * STAGE3_FLOATS * 4)   // 156672 B (dynamic, opt-in)

#define CP_ASYNC16(dst, src) \
    asm volatile("cp.async.cg.shared.global [%0], [%1], 16;\n" :: "r"(dst), "l"(src))
#define CP_COMMIT() asm volatile("cp.async.commit_group;\n")
#define CP_WAIT1()  asm volatile("cp.async.wait_group 1;\n")

__device__ __forceinline__ uint32_t smem_u32(const void* p) {
    return (uint32_t)__cvta_generic_to_shared(p);
}

// ---------------------------------------------------------------------------
// init: h0 = c0 = mean over the 16 spatial positions of A
// ---------------------------------------------------------------------------
__global__ __launch_bounds__(128) void init_kernel(const float* __restrict__ A) {
    int n = blockIdx.x, tid = threadIdx.x;
    const float4* base = (const float4*)(A + (size_t)n * Hh * 16);
#pragma unroll
    for (int i = 0; i < 4; i++) {
        int r = tid + i * 128;
        float4 v0 = base[r * 4 + 0], v1 = base[r * 4 + 1];
        float4 v2 = base[r * 4 + 2], v3 = base[r * 4 + 3];
        float s = (v0.x + v0.y + v0.z + v0.w) + (v1.x + v1.y + v1.z + v1.w)
                + (v2.x + v2.y + v2.z + v2.w) + (v3.x + v3.y + v3.z + v3.w);
        float m = s * (1.0f / 16.0f);
        g_h[0][n * Hh + r] = m;
        g_c[0][n * Hh + r] = m;
    }
}

// ---------------------------------------------------------------------------
// ONE-TIME big GEMM: g_xw = x @ Wx for all (n,t) rows. M = Nb*Tt = 32768.
// Grid (16, 512) = 8192 CTAs; proven round-4 CTA body, 32 K-iters, 2 CTAs/SM.
// ---------------------------------------------------------------------------
__global__ __launch_bounds__(256, 2) void xw_all_kernel(
    const float* __restrict__ x, const float* __restrict__ Wx)
{
    __shared__ __align__(16) float sm[NSTAGES * STAGE_FLOATS];
    const int tid = threadIdx.x;
    const int j0 = blockIdx.x * 32;
    const int m0 = blockIdx.y * 64;
    const float* xbase = x + (size_t)m0 * Dd;
    const int am = tid >> 2, akq = (tid & 3) * 4;

    const int lane = tid & 31, wid = tid >> 5;
    const int wm = wid & 1, wn = wid >> 1;
    const int gid = lane >> 2, tg = lane & 3;

    float acc[2][4][4];
#pragma unroll
    for (int fm = 0; fm < 2; fm++)
#pragma unroll
        for (int fn = 0; fn < 4; fn++)
#pragma unroll
            for (int e = 0; e < 4; e++) acc[fm][fn][e] = 0.f;

    auto issue = [&](int i) {
        float* stg = sm + (i % NSTAGES) * STAGE_FLOATS;
        int kl = i << 4;
        const float* asrc = xbase + (size_t)am * Dd + kl + akq;
        CP_ASYNC16(smem_u32(stg + am * ASTR + akq), asrc);
        float* Bst = stg + A_FLOATS;
#pragma unroll
        for (int j = 0; j < 2; j++) {
            int e = tid + j * 256;
            int k = e >> 5, n4 = e & 31;
            const float* bsrc = Wx + (size_t)(kl + k) * FH + (n4 >> 3) * 512 + j0 + (n4 & 7) * 4;
            CP_ASYNC16(smem_u32(Bst + k * BSTR + n4 * 4), bsrc);
        }
    };

    issue(0); CP_COMMIT();
    issue(1); CP_COMMIT();

    for (int i = 0; i < 32; i++) {
        CP_WAIT1();
        __syncthreads();
        const float* As = sm + (i % NSTAGES) * STAGE_FLOATS;
        const float* Bs = As + A_FLOATS;
#pragma unroll
        for (int k8 = 0; k8 < 2; k8++) {
            int kb = k8 * 8;
            uint32_t a[2][4], bf[4][2];
#pragma unroll
            for (int fm = 0; fm < 2; fm++) {
                int row = wm * 32 + fm * 16 + gid;
                a[fm][0] = __float_as_uint(As[row * ASTR + kb + tg]);
                a[fm][1] = __float_as_uint(As[(row + 8) * ASTR + kb + tg]);
                a[fm][2] = __float_as_uint(As[row * ASTR + kb + tg + 4]);
                a[fm][3] = __float_as_uint(As[(row + 8) * ASTR + kb + tg + 4]);
            }
#pragma unroll
            for (int fn = 0; fn < 4; fn++) {
                int col = wn * 32 + fn * 8 + gid;
                bf[fn][0] = __float_as_uint(Bs[(kb + tg) * BSTR + col]);
                bf[fn][1] = __float_as_uint(Bs[(kb + tg + 4) * BSTR + col]);
            }
#pragma unroll
            for (int fm = 0; fm < 2; fm++)
#pragma unroll
                for (int fn = 0; fn < 4; fn++) {
                    asm volatile(
                        "mma.sync.aligned.m16n8k8.row.col.f32.tf32.tf32.f32 "
                        "{%0,%1,%2,%3}, {%4,%5,%6,%7}, {%8,%9}, {%0,%1,%2,%3};\n"
                        : "+f"(acc[fm][fn][0]), "+f"(acc[fm][fn][1]),
                          "+f"(acc[fm][fn][2]), "+f"(acc[fm][fn][3])
                        : "r"(a[fm][0]), "r"(a[fm][1]), "r"(a[fm][2]), "r"(a[fm][3]),
                          "r"(bf[fn][0]), "r"(bf[fn][1]));
                }
        }
        if (i + 2 < 32) issue(i + 2);
        CP_COMMIT();
    }

#pragma unroll
    for (int fm = 0; fm < 2; fm++)
#pragma unroll
        for (int fn = 0; fn < 4; fn++) {
            int R = wm * 32 + fm * 16 + gid;
            int fc = wn * 512 + j0 + fn * 8 + tg * 2;
            *(float2*)&g_xw[(size_t)(m0 + R) * FH + fc] =
                make_float2(acc[fm][fn][0], acc[fm][fn][1]);
            *(float2*)&g_xw[(size_t)(m0 + R + 8) * FH + fc] =
                make_float2(acc[fm][fn][2], acc[fm][fn][3]);
        }
}

// ---------------------------------------------------------------------------
// attention (proven round-4 version): one block per batch row, 128 threads,
// A row in registers, read once.
// ---------------------------------------------------------------------------
__global__ __launch_bounds__(128) void attn_kernel(const float* __restrict__ A, int pi) {
    int n = blockIdx.x, tid = threadIdx.x;
    int lane = tid & 31, warp = tid >> 5;
    const float* hbuf = g_h[pi] + (size_t)n * Hh;
    const float4* base = (const float4*)(A + (size_t)n * Hh * 16);

    float Av[4][16];
    float hv[4];
    float part[16];
#pragma unroll
    for (int p = 0; p < 16; p++) part[p] = 0.f;

#pragma unroll
    for (int i = 0; i < 4; i++) {
        int r = tid + i * 128;
#pragma unroll
        for (int q = 0; q < 4; q++) {
            float4 v = base[r * 4 + q];
            Av[i][q * 4 + 0] = v.x; Av[i][q * 4 + 1] = v.y;
            Av[i][q * 4 + 2] = v.z; Av[i][q * 4 + 3] = v.w;
        }
        hv[i] = hbuf[r];
#pragma unroll
        for (int p = 0; p < 16; p++) part[p] += hv[i] * Av[i][p];
    }

#pragma unroll
    for (int off = 16; off >= 1; off >>= 1)
#pragma unroll
        for (int p = 0; p < 16; p++)
            part[p] += __shfl_xor_sync(0xffffffffu, part[p], off);

    __shared__ float red[4][16];
    __shared__ float w[16];
    if (lane == 0) {
#pragma unroll
        for (int p = 0; p < 16; p++) red[warp][p] = part[p];
    }
    __syncthreads();
    if (tid == 0) {
        const float scale = 0.044194173824159216f;  // 1/sqrt(512)
        float sc[16];
        float mx = -1e30f;
#pragma unroll
        for (int p = 0; p < 16; p++) {
            sc[p] = (red[0][p] + red[1][p] + red[2][p] + red[3][p]) * scale;
            mx = fmaxf(mx, sc[p]);
        }
        float s = 0.f;
#pragma unroll
        for (int p = 0; p < 16; p++) { float e = expf(sc[p] - mx); w[p] = e; s += e; }
        float inv = 1.f / s;
#pragma unroll
        for (int p = 0; p < 16; p++) w[p] *= inv;
    }
    __syncthreads();

    float wl[16];
#pragma unroll
    for (int p = 0; p < 16; p++) wl[p] = w[p];
    float* ao = g_attn + (size_t)n * Hh;
#pragma unroll
    for (int i = 0; i < 4; i++) {
        float s = 0.f;
#pragma unroll
        for (int p = 0; p < 16; p++) s += Av[i][p] * wl[p];
        ao[tid + i * 128] = s;
    }
}

// ---------------------------------------------------------------------------
// sequential step: K=1024 in 16 iterations of K=64 (16 barrier events).
// acc initialized from g_xw (row n*Tt + t). MMA order unchanged ->
// identical numerics. Dynamic smem (153 KB, opt-in).
// ---------------------------------------------------------------------------
__global__ __launch_bounds__(256, 1) void step_kernel(
    const float* __restrict__ Wh, const float* __restrict__ Wattn,
    const float* __restrict__ bias, float* __restrict__ out, int t, int pi)
{
    extern __shared__ __align__(16) float sm[];
    const int tid = threadIdx.x;
    const int j0 = blockIdx.x * 32;
    const int n0 = blockIdx.y * 64;
    const float* h_in = g_h[pi];
    const float* c_in = g_c[pi];
    float* h_out = g_h[pi ^ 1];
    float* c_out = g_c[pi ^ 1];

    const int lane = tid & 31, wid = tid >> 5;
    const int wm = wid & 1, wn = wid >> 1;
    const int gid = lane >> 2, tg = lane & 3;

    // acc init from g_xw (row m = n*Tt + t)
    float acc[2][4][4];
#pragma unroll
    for (int fm = 0; fm < 2; fm++)
#pragma unroll
        for (int fn = 0; fn < 4; fn++) {
            int R = wm * 32 + fm * 16 + gid;
            int fc = wn * 512 + j0 + fn * 8 + tg * 2;
            float2 v0 = *(const float2*)&g_xw[((size_t)(n0 + R) * Tt + t) * FH + fc];
            float2 v1 = *(const float2*)&g_xw[((size_t)(n0 + R + 8) * Tt + t) * FH + fc];
            acc[fm][fn][0] = v0.x; acc[fm][fn][1] = v0.y;
            acc[fm][fn][2] = v1.x; acc[fm][fn][3] = v1.y;
        }

    // stage issue: K=64 slab. A tile 64x64 (4 chunks/thread), B 64x128
    // (8 chunks/thread).
    auto issue = [&](int i) {
        float* stg = sm + (i % 3) * STAGE3_FLOATS;
        int seg = i >> 3;                 // 0..7 -> h/Wh, 8..15 -> attn/Wattn
        int kl = (i & 7) << 6;            // K offset within segment
        const float* Ab; const float* W;
        if (seg == 0) { Ab = h_in   + (size_t)n0 * Hh; W = Wh; }
        else          { Ab = g_attn + (size_t)n0 * Hh; W = Wattn; }
#pragma unroll
        for (int j = 0; j < 4; j++) {
            int e = tid + j * 256;
            int row = e >> 4, kc = e & 15;   // 64 rows x 16 chunks
            const float* asrc = Ab + (size_t)row * Hh + kl + kc * 4;
            CP_ASYNC16(smem_u32(stg + row * ASTR3 + kc * 4), asrc);
        }
        float* Bst = stg + A3_FLOATS;
#pragma unroll
        for (int j = 0; j < 8; j++) {
            int e = tid + j * 256;
            int k = e >> 5, n4 = e & 31;     // 64 k-rows x 32 chunks
            const float* bsrc = W + (size_t)(kl + k) * FH + (n4 >> 3) * 512 + j0 + (n4 & 7) * 4;
            CP_ASYNC16(smem_u32(Bst + k * BSTR + n4 * 4), bsrc);
        }
    };

    issue(0); CP_COMMIT();
    issue(1); CP_COMMIT();

    for (int i = 0; i < 16; i++) {
        CP_WAIT1();
        __syncthreads();
        const float* As = sm + (i % 3) * STAGE3_FLOATS;
        const float* Bs = As + A3_FLOATS;
#pragma unroll
        for (int k8 = 0; k8 < 8; k8++) {
            int kb = k8 * 8;
            uint32_t a[2][4], bf[4][2];
#pragma unroll
            for (int fm = 0; fm < 2; fm++) {
                int row = wm * 32 + fm * 16 + gid;
                a[fm][0] = __float_as_uint(As[row * ASTR3 + kb + tg]);
                a[fm][1] = __float_as_uint(As[(row + 8) * ASTR3 + kb + tg]);
                a[fm][2] = __float_as_uint(As[row * ASTR3 + kb + tg + 4]);
                a[fm][3] = __float_as_uint(As[(row + 8) * ASTR3 + kb + tg + 4]);
            }
#pragma unroll
            for (int fn = 0; fn < 4; fn++) {
                int col = wn * 32 + fn * 8 + gid;
                bf[fn][0] = __float_as_uint(Bs[(kb + tg) * BSTR + col]);
                bf[fn][1] = __float_as_uint(Bs[(kb + tg + 4) * BSTR + col]);
            }
#pragma unroll
            for (int fm = 0; fm < 2; fm++)
#pragma unroll
                for (int fn = 0; fn < 4; fn++) {
                    asm volatile(
                        "mma.sync.aligned.m16n8k8.row.col.f32.tf32.tf32.f32 "
                        "{%0,%1,%2,%3}, {%4,%5,%6,%7}, {%8,%9}, {%0,%1,%2,%3};\n"
                        : "+f"(acc[fm][fn][0]), "+f"(acc[fm][fn][1]),
                          "+f"(acc[fm][fn][2]), "+f"(acc[fm][fn][3])
                        : "r"(a[fm][0]), "r"(a[fm][1]), "r"(a[fm][2]), "r"(a[fm][3]),
                          "r"(bf[fn][0]), "r"(bf[fn][1]));
                }
        }
        if (i + 2 < 16) issue(i + 2);
        CP_COMMIT();
    }

    __syncthreads();
    // stash a-tile (64 x 128) in smem for gate gathering
    float (*atile)[132] = (float(*)[132])sm;
#pragma unroll
    for (int fm = 0; fm < 2; fm++)
#pragma unroll
        for (int fn = 0; fn < 4; fn++) {
            int R = wm * 32 + fm * 16 + gid, C = wn * 32 + fn * 8 + tg * 2;
            atile[R][C]         = acc[fm][fn][0];
            atile[R][C + 1]     = acc[fm][fn][1];
            atile[R + 8][C]     = acc[fm][fn][2];
            atile[R + 8][C + 1] = acc[fm][fn][3];
        }
    __syncthreads();

    {
        int col = tid & 31;
        int r0 = tid >> 5;
        float bi = bias[j0 + col];
        float bff = bias[512 + j0 + col];
        float bo = bias[1024 + j0 + col];
        float bg = bias[1536 + j0 + col];
#pragma unroll
        for (int q = 0; q < 8; q++) {
            int row = r0 + q * 8;
            float vi = atile[row][col]      + bi;
            float vf = atile[row][col + 32] + bff;
            float vo = atile[row][col + 64] + bo;
            float vg = atile[row][col + 96] + bg;
            float ig = 1.f / (1.f + expf(-vi));
            float fg = 1.f / (1.f + expf(-vf));
            float og = 1.f / (1.f + expf(-vo));
            float gg = tanhf(vg);
            int n = n0 + row, hc = j0 + col;
            float cold = c_in[n * Hh + hc];
            float cn = fg * cold + ig * gg;
            float hn = og * tanhf(cn);
            c_out[n * Hh + hc] = cn;
            h_out[n * Hh + hc] = hn;
            out[((size_t)n * Tt + t) * Hh + hc] = hn;
        }
    }
}

// ---------------------------------------------------------------------------
extern "C" void kernel_launch(void* const* d_in, const int* in_sizes, int n_in,
                              void* d_out, int out_size) {
    const float* x     = (const float*)d_in[0];
    const float* A     = (const float*)d_in[1];
    const float* Wx    = (const float*)d_in[2];
    const float* Wh    = (const float*)d_in[3];
    const float* Wattn = (const float*)d_in[4];
    const float* b     = (const float*)d_in[5];
    float* out = (float*)d_out;

    static int smem_configured = 0;
    if (!smem_configured) {
        cudaFuncSetAttribute(step_kernel,
                             cudaFuncAttributeMaxDynamicSharedMemorySize,
                             STEP_SMEM_BYTES);
        smem_configured = 1;
    }

    xw_all_kernel<<<dim3(16, 512), 256>>>(x, Wx);   // no deps on the recurrence
    init_kernel<<<Nb, 128>>>(A);
    for (int t = 0; t < Tt; t++) {
        int pi = t & 1;
        attn_kernel<<<Nb, 128>>>(A, pi);
        step_kernel<<<dim3(16, 8), 256, STEP_SMEM_BYTES>>>(Wh, Wattn, b, out, t, pi);
    }
}